// round 16
// baseline (speedup 1.0000x reference)
#include <cuda_runtime.h>
#include <cuda_bf16.h>
#include <math.h>

#define N 4096
#define NF 19
#define PSTRIDE 20
#define NUM_LABELS 10
#define BIG 1e30f

__device__ float g_D[(size_t)N * N];
__device__ float g_pts[N * PSTRIDE];
__device__ int   g_eu[N], g_ev[N];
__device__ float g_ed[N];
__device__ int   g_us[N], g_vs[N];
__device__ float g_ds[N];

#define OFF_EMST 1
#define OFF_EU   12286
#define OFF_EV   16381
#define OFF_D    20476
#define OFF_RP   24571
#define OFF_RN   28666

// ---------------- kernel 1: build points (NUMERICS FROZEN) ----------------
__global__ void k_pts(const float* __restrict__ inp) {
    int n = blockIdx.x * blockDim.x + threadIdx.x;
    if (n >= N) return;
    int z = n >> 8, y = (n >> 4) & 15, x = n & 15;
    float p[NF];
    p[0] = __fmul_rn((float)z, 0.01f);
    p[1] = __fmul_rn((float)y, 0.01f);
    p[2] = __fmul_rn((float)x, 0.01f);
#pragma unroll
    for (int c = 0; c < 16; c++) p[3 + c] = inp[c * N + n];

    float xs[NF];
#pragma unroll
    for (int k = 0; k < NF; k++) xs[k] = __fmul_rn(p[k], p[k]);
    float y0 = __fadd_rn(xs[0], xs[16]);
    float y1 = __fadd_rn(xs[1], xs[17]);
    float y2 = __fadd_rn(xs[2], xs[18]);
    float z0 = __fadd_rn(y0,    xs[8]);
    float z1 = __fadd_rn(y1,    xs[9]);
    float z2 = __fadd_rn(y2,    xs[10]);
    float z3 = __fadd_rn(xs[3], xs[11]);
    float z4 = __fadd_rn(xs[4], xs[12]);
    float z5 = __fadd_rn(xs[5], xs[13]);
    float z6 = __fadd_rn(xs[6], xs[14]);
    float z7 = __fadd_rn(xs[7], xs[15]);
    float w0 = __fadd_rn(z0, z4);
    float w1 = __fadd_rn(z1, z5);
    float w2 = __fadd_rn(z2, z6);
    float w3 = __fadd_rn(z3, z7);
    float v0 = __fadd_rn(w0, w2);
    float v1 = __fadd_rn(w1, w3);
    float sq = __fadd_rn(v0, v1);

#pragma unroll
    for (int k = 0; k < NF; k++) g_pts[n * PSTRIDE + k] = p[k];
    g_pts[n * PSTRIDE + 19] = sq;
}

// ---------------- kernel 2: dense distance matrix, SYMMETRIC ---------------
// dot(i,j)==dot(j,i) bitwise (same k-order FMA) and sq_i+sq_j commutes, so
// D is bitwise symmetric: compute upper-triangle blocks only, mirror via a
// conflict-free smem transpose. Halves the MUFU(sqrt) + FMA work.
__global__ void k_dist() {
    int i0 = blockIdx.y * 32, j0 = blockIdx.x * 32;
    if (j0 < i0) return;
    __shared__ float A[32][21];
    __shared__ float B[32][21];
    __shared__ float T[32][33];
    int t = threadIdx.y * 32 + threadIdx.x;
    for (int s = t; s < 32 * PSTRIDE; s += 256) {
        int r = s / PSTRIDE, c = s % PSTRIDE;
        A[r][c] = g_pts[(i0 + r) * PSTRIDE + c];
        B[r][c] = g_pts[(j0 + r) * PSTRIDE + c];
    }
    __syncthreads();
    int j = threadIdx.x;
#pragma unroll
    for (int r = 0; r < 4; r++) {
        int i = threadIdx.y + r * 8;
        float dot = 0.f;
#pragma unroll
        for (int k = 0; k < NF; k++) dot = __fmaf_rn(A[i][k], B[j][k], dot);
        float t1 = __fadd_rn(A[i][19], B[j][19]);
        float t2 = __fmul_rn(2.0f, dot);
        float d2 = __fadd_rn(t1, -t2);
        float dv = __fsqrt_rn(fmaxf(d2, 1e-12f));
        g_D[(size_t)(i0 + i) * N + (j0 + j)] = dv;
        T[j][i] = dv;                      // banks: 33*j+i, all distinct
    }
    if (j0 > i0) {
        __syncthreads();
#pragma unroll
        for (int r = 0; r < 4; r++) {
            int jl = threadIdx.y + r * 8;
            g_D[(size_t)(j0 + jl) * N + (i0 + threadIdx.x)] = T[jl][threadIdx.x];
        }
    }
}

// ---------------- kernel 3: Prim, 256 thr x 16 cols, scalar tree argmin ----
// Per-warp fixed costs (REDUX/STS/barrier) dominate -> 8 warps. Local argmin
// is a scalar adjacent-pair tournament (depth 4); at every comparison left's
// index set < right's, so tie->left == lowest-index (jnp.argmin semantics).
__global__ void __launch_bounds__(256) k_prim() {
    int tid  = threadIdx.x;
    int lane = tid & 31;
    int warp = tid >> 5;
    float md[16];
    int mf[16];
    unsigned intree = 0;
    {
        const float4* r0 = (const float4*)g_D;
#pragma unroll
        for (int i = 0; i < 4; i++) {
            float4 r = r0[tid * 4 + i];
            md[i*4+0]=r.x; md[i*4+1]=r.y; md[i*4+2]=r.z; md[i*4+3]=r.w;
        }
#pragma unroll
        for (int k = 0; k < 16; k++) mf[k] = 0;
        if (tid == 0) { md[0] = BIG; intree = 1; }
    }
    __shared__ unsigned long long wkey[2][8];

    for (int it = 0; it < N - 1; ++it) {
        // scalar tournament argmin over 16 local entries (depth 4)
        unsigned bb[16];
#pragma unroll
        for (int k = 0; k < 16; k++) bb[k] = __float_as_uint(md[k]);
        unsigned b1[8], i1[8];
#pragma unroll
        for (int k = 0; k < 8; k++) {
            bool tk = bb[2*k+1] < bb[2*k];
            b1[k] = tk ? bb[2*k+1] : bb[2*k];
            i1[k] = tk ? (unsigned)(2*k+1) : (unsigned)(2*k);
        }
        unsigned b2a[4], i2a[4];
#pragma unroll
        for (int k = 0; k < 4; k++) {
            bool tk = b1[2*k+1] < b1[2*k];
            b2a[k] = tk ? b1[2*k+1] : b1[2*k];
            i2a[k] = tk ? i1[2*k+1] : i1[2*k];
        }
        bool ta = b2a[1] < b2a[0];
        unsigned b3a = ta ? b2a[1] : b2a[0];
        unsigned i3a = ta ? i2a[1] : i2a[0];
        bool tb = b2a[3] < b2a[2];
        unsigned b3b = tb ? b2a[3] : b2a[2];
        unsigned i3b = tb ? i2a[3] : i2a[2];
        bool tc = b3b < b3a;
        unsigned vb = tc ? b3b : b3a;
        unsigned vi = (unsigned)(tid * 16) + (tc ? i3b : i3a);

        unsigned m  = __reduce_min_sync(0xFFFFFFFFu, vb);
        unsigned c  = (vb == m) ? vi : 0xFFFFFFFFu;
        unsigned mi = __reduce_min_sync(0xFFFFFFFFu, c);
        if (lane == 0)
            wkey[it & 1][warp] = (((unsigned long long)m) << 32) | mi;
        __syncthreads();
        unsigned long long k2 = wkey[it & 1][lane & 7];
        unsigned b3 = (unsigned)(k2 >> 32);
        unsigned m2 = __reduce_min_sync(0xFFFFFFFFu, b3);
        unsigned c2 = (b3 == m2) ? (unsigned)k2 : 0xFFFFFFFFu;
        unsigned v  = __reduce_min_sync(0xFFFFFFFFu, c2);
        float d = __uint_as_float(m2);

        // 4 independent row loads, issued ASAP
        const float4* rowv = (const float4*)(g_D + (size_t)v * N);
        float4 r0v = rowv[tid * 4 + 0];
        float4 r1v = rowv[tid * 4 + 1];
        float4 r2v = rowv[tid * 4 + 2];
        float4 r3v = rowv[tid * 4 + 3];

        // off-critical-path: prefetch best non-winner candidate's row
        {
            bool iswin = (b3 == m2) && ((unsigned)k2 == v);
            unsigned b4 = iswin ? 0xFFFFFFFFu : b3;
            unsigned m3 = __reduce_min_sync(0xFFFFFFFFu, b4);
            unsigned c3 = (b4 == m3) ? (unsigned)k2 : 0xFFFFFFFFu;
            unsigned v2 = __reduce_min_sync(0xFFFFFFFFu, c3);
            v2 = (v2 > 4095u) ? 4095u : v2;
            const char* pf = (const char*)(g_D + (size_t)v2 * N) + tid * 64;
            asm volatile("prefetch.global.L1 [%0];" :: "l"(pf));
        }

        if ((v >> 4) == (unsigned)tid) {
            int k = (int)(v & 15u);
#pragma unroll
            for (int q = 0; q < 16; q++) if (q == k) {
                g_eu[it] = mf[q];
                md[q] = BIG;
            }
            g_ev[it] = (int)v;
            g_ed[it] = d;
            intree |= (1u << k);
        }
        float dr[16] = { r0v.x, r0v.y, r0v.z, r0v.w,
                         r1v.x, r1v.y, r1v.z, r1v.w,
                         r2v.x, r2v.y, r2v.z, r2v.w,
                         r3v.x, r3v.y, r3v.z, r3v.w };
#pragma unroll
        for (int k = 0; k < 16; k++) {
            if (!((intree >> k) & 1) && dr[k] < md[k]) { md[k] = dr[k]; mf[k] = (int)v; }
        }
    }
}

// ---------------- kernel 4: STABLE bitonic sort of 4095 edges + outputs ----
__global__ void __launch_bounds__(1024) k_sort(float* __restrict__ out) {
    __shared__ unsigned long long key[N];
    int tid = threadIdx.x;
    for (int e = tid; e < N; e += 1024) {
        if (e < N - 1) {
            key[e] = (((unsigned long long)__float_as_uint(g_ed[e])) << 32)
                     | (unsigned)e;
        } else {
            key[e] = 0xFFFFFFFFFFFFFFFFull;
        }
    }
    __syncthreads();
    for (int sz = 2; sz <= N; sz <<= 1) {
        for (int j = sz >> 1; j > 0; j >>= 1) {
            for (int i = tid; i < N; i += 1024) {
                int l = i ^ j;
                if (l > i) {
                    bool asc = ((i & sz) == 0);
                    unsigned long long ki = key[i], kl = key[l];
                    if ((ki > kl) == asc) { key[i] = kl; key[l] = ki; }
                }
            }
            __syncthreads();
        }
    }
    for (int e = tid; e < N - 1; e += 1024) {
        unsigned long long k = key[e];
        int src = (int)(unsigned)(k & 0xFFFFFFFFu);
        float fd = __uint_as_float((unsigned)(k >> 32));
        int u = g_eu[src], v = g_ev[src];
        float fu = (float)u, fv = (float)v;
        out[OFF_EMST + 3 * e + 0] = fu;
        out[OFF_EMST + 3 * e + 1] = fv;
        out[OFF_EMST + 3 * e + 2] = fd;
        out[OFF_EU + e] = fu;
        out[OFF_EV + e] = fv;
        out[OFF_D + e] = fd;
        g_us[e] = u;
        g_vs[e] = v;
        g_ds[e] = fd;
    }
}

// ---------------- kernel 5: Kruskal, single thread, 4x unrolled ------------
__global__ void __launch_bounds__(1024) k_kruskal(const int* __restrict__ labels,
                                                  float* __restrict__ out) {
    extern __shared__ int sm[];
    int*   parent = sm;                       // N
    int*   counts = sm + N;                   // N*10
    int*   seu    = sm + N + N * NUM_LABELS;  // N
    int*   sev    = seu + N;                  // N
    float* sd     = (float*)(sev + N);        // N
    __shared__ int cbin[16];

    int tid = threadIdx.x;
    if (tid < 16) cbin[tid] = 0;
    for (int i = tid; i < N * NUM_LABELS; i += 1024) counts[i] = 0;
    __syncthreads();
    for (int n = tid; n < N; n += 1024) {
        parent[n] = n;
        int l = labels[n];
        counts[n * NUM_LABELS + l] = 1;
        atomicAdd(&cbin[l], 1);
    }
    for (int e = tid; e < N - 1; e += 1024) {
        seu[e] = g_us[e]; sev[e] = g_vs[e]; sd[e] = g_ds[e];
    }
    __syncthreads();
    if (tid != 0) return;

    float inv_tpf, inv_tnf;
    {
        long long tp = 0;
#pragma unroll
        for (int l = 0; l < NUM_LABELS; l++)
            tp += (long long)cbin[l] * (cbin[l] - 1) / 2;
        long long pairs = (long long)N * (N - 1) / 2;
        inv_tpf = 1.0f / (float)tp;
        inv_tnf = 1.0f / (float)(pairs - tp);
    }

#define KEDGE(E, ACC) do {                                                    \
        int x0 = seu[E];                                                      \
        int x1 = sev[E];                                                      \
        int p0 = parent[x0];                                                  \
        int p1 = parent[x1];                                                  \
        while (p0 != x0) { int g = parent[p0]; parent[x0] = g; x0 = p0; p0 = g; } \
        while (p1 != x1) { int g = parent[p1]; parent[x1] = g; x1 = p1; p1 = g; } \
        int a = x0, b = x1;                                                   \
        const int2* ra2 = (const int2*)(counts + a * NUM_LABELS);             \
        const int2* rb2 = (const int2*)(counts + b * NUM_LABELS);             \
        int2 av[5], bv[5], mg[5];                                             \
        int pos = 0, sa = 0, sb = 0;                                          \
        _Pragma("unroll")                                                     \
        for (int i = 0; i < 5; i++) { av[i] = ra2[i]; bv[i] = rb2[i]; }       \
        _Pragma("unroll")                                                     \
        for (int i = 0; i < 5; i++) {                                         \
            pos += av[i].x * bv[i].x + av[i].y * bv[i].y;                     \
            sa  += av[i].x + av[i].y;                                         \
            sb  += bv[i].x + bv[i].y;                                         \
            mg[i].x = av[i].x + bv[i].x;                                      \
            mg[i].y = av[i].y + bv[i].y;                                      \
        }                                                                     \
        int r  = (sa >= sb) ? a : b;                                          \
        int s2 = (sa >= sb) ? b : a;                                          \
        int2* rr2 = (int2*)(counts + r * NUM_LABELS);                         \
        int2* rs2 = (int2*)(counts + s2 * NUM_LABELS);                        \
        _Pragma("unroll")                                                     \
        for (int i = 0; i < 5; i++) { rr2[i] = mg[i]; rs2[i] = make_int2(0, 0); } \
        parent[s2] = r;                                                       \
        int neg = sa * sb - pos;                                              \
        float d = sd[E];                                                      \
        float rp = (float)pos * inv_tpf;                                      \
        float rn = (float)neg * inv_tnf;                                      \
        out[OFF_RP + (E)] = rp;                                               \
        out[OFF_RN + (E)] = rn;                                               \
        float mm = fmaxf(0.0f, 0.1f - d);                                     \
        ACC += (double)(rp * d * d + rn * mm * mm);                           \
    } while (0)

    double acc0 = 0.0, acc1 = 0.0, acc2 = 0.0, acc3 = 0.0;
    int e = 0;
    for (; e + 4 <= N - 1; e += 4) {
        KEDGE(e + 0, acc0);
        KEDGE(e + 1, acc1);
        KEDGE(e + 2, acc2);
        KEDGE(e + 3, acc3);
    }
    for (; e < N - 1; e++) KEDGE(e, acc0);
#undef KEDGE
    out[0] = (float)((acc0 + acc1) + (acc2 + acc3));
}

// ---------------- launch ----------------
extern "C" void kernel_launch(void* const* d_in, const int* in_sizes, int n_in,
                              void* d_out, int out_size) {
    const float* input  = (const float*)d_in[0];
    const int*   target = (const int*)d_in[1];
    float* out = (float*)d_out;

    static const size_t KSMEM = (size_t)(N + N * NUM_LABELS + 3 * N) * 4;
    cudaFuncSetAttribute(k_kruskal, cudaFuncAttributeMaxDynamicSharedMemorySize,
                         (int)KSMEM);

    k_pts<<<4, 1024>>>(input);
    k_dist<<<dim3(128, 128), dim3(32, 8)>>>();
    k_prim<<<1, 256>>>();
    k_sort<<<1, 1024>>>(out);
    k_kruskal<<<1, 1024, KSMEM>>>(target, out);
}

// round 17
// speedup vs baseline: 1.1464x; 1.1464x over previous
#include <cuda_runtime.h>
#include <cuda_bf16.h>
#include <math.h>

#define N 4096
#define NF 19
#define PSTRIDE 20
#define NUM_LABELS 10
#define BIG 1e30f

__device__ float g_D[(size_t)N * N];
__device__ float g_pts[N * PSTRIDE];
__device__ int   g_eu[N], g_ev[N];
__device__ float g_ed[N];
__device__ int   g_us[N], g_vs[N];
__device__ float g_ds[N];

#define OFF_EMST 1
#define OFF_EU   12286
#define OFF_EV   16381
#define OFF_D    20476
#define OFF_RP   24571
#define OFF_RN   28666

// ---------------- kernel 1: build points (NUMERICS FROZEN) ----------------
__global__ void k_pts(const float* __restrict__ inp) {
    int n = blockIdx.x * blockDim.x + threadIdx.x;
    if (n >= N) return;
    int z = n >> 8, y = (n >> 4) & 15, x = n & 15;
    float p[NF];
    p[0] = __fmul_rn((float)z, 0.01f);
    p[1] = __fmul_rn((float)y, 0.01f);
    p[2] = __fmul_rn((float)x, 0.01f);
#pragma unroll
    for (int c = 0; c < 16; c++) p[3 + c] = inp[c * N + n];

    float xs[NF];
#pragma unroll
    for (int k = 0; k < NF; k++) xs[k] = __fmul_rn(p[k], p[k]);
    float y0 = __fadd_rn(xs[0], xs[16]);
    float y1 = __fadd_rn(xs[1], xs[17]);
    float y2 = __fadd_rn(xs[2], xs[18]);
    float z0 = __fadd_rn(y0,    xs[8]);
    float z1 = __fadd_rn(y1,    xs[9]);
    float z2 = __fadd_rn(y2,    xs[10]);
    float z3 = __fadd_rn(xs[3], xs[11]);
    float z4 = __fadd_rn(xs[4], xs[12]);
    float z5 = __fadd_rn(xs[5], xs[13]);
    float z6 = __fadd_rn(xs[6], xs[14]);
    float z7 = __fadd_rn(xs[7], xs[15]);
    float w0 = __fadd_rn(z0, z4);
    float w1 = __fadd_rn(z1, z5);
    float w2 = __fadd_rn(z2, z6);
    float w3 = __fadd_rn(z3, z7);
    float v0 = __fadd_rn(w0, w2);
    float v1 = __fadd_rn(w1, w3);
    float sq = __fadd_rn(v0, v1);

#pragma unroll
    for (int k = 0; k < NF; k++) g_pts[n * PSTRIDE + k] = p[k];
    g_pts[n * PSTRIDE + 19] = sq;
}

// ---------------- kernel 2: dense distance matrix, SYMMETRIC ---------------
// dot(i,j)==dot(j,i) bitwise (same k-order FMA) and sq_i+sq_j commutes, so
// D is bitwise symmetric: compute upper-triangle blocks only, mirror via a
// conflict-free smem transpose. Halves the MUFU(sqrt) + FMA work.
__global__ void k_dist() {
    int i0 = blockIdx.y * 32, j0 = blockIdx.x * 32;
    if (j0 < i0) return;
    __shared__ float A[32][21];
    __shared__ float B[32][21];
    __shared__ float T[32][33];
    int t = threadIdx.y * 32 + threadIdx.x;
    for (int s = t; s < 32 * PSTRIDE; s += 256) {
        int r = s / PSTRIDE, c = s % PSTRIDE;
        A[r][c] = g_pts[(i0 + r) * PSTRIDE + c];
        B[r][c] = g_pts[(j0 + r) * PSTRIDE + c];
    }
    __syncthreads();
    int j = threadIdx.x;
#pragma unroll
    for (int r = 0; r < 4; r++) {
        int i = threadIdx.y + r * 8;
        float dot = 0.f;
#pragma unroll
        for (int k = 0; k < NF; k++) dot = __fmaf_rn(A[i][k], B[j][k], dot);
        float t1 = __fadd_rn(A[i][19], B[j][19]);
        float t2 = __fmul_rn(2.0f, dot);
        float d2 = __fadd_rn(t1, -t2);
        float dv = __fsqrt_rn(fmaxf(d2, 1e-12f));
        g_D[(size_t)(i0 + i) * N + (j0 + j)] = dv;
        T[j][i] = dv;                      // banks: 33*j+i, all distinct
    }
    if (j0 > i0) {
        __syncthreads();
#pragma unroll
        for (int r = 0; r < 4; r++) {
            int jl = threadIdx.y + r * 8;
            g_D[(size_t)(j0 + jl) * N + (i0 + threadIdx.x)] = T[jl][threadIdx.x];
        }
    }
}

// ---------------- kernel 3: Prim, 512 thr x 8 cols, tree argmin (R15) ------
__global__ void __launch_bounds__(512) k_prim() {
    int tid  = threadIdx.x;
    int lane = tid & 31;
    int warp = tid >> 5;
    float md[8];
    int mf[8];
    unsigned intree = 0;
    {
        const float4* r0 = (const float4*)g_D;
        float4 a = r0[tid * 2];
        float4 b = r0[tid * 2 + 1];
        md[0]=a.x; md[1]=a.y; md[2]=a.z; md[3]=a.w;
        md[4]=b.x; md[5]=b.y; md[6]=b.z; md[7]=b.w;
#pragma unroll
        for (int k = 0; k < 8; k++) mf[k] = 0;
        if (tid == 0) { md[0] = BIG; intree = 1; }
    }
    __shared__ unsigned long long wkey[2][16];

    for (int it = 0; it < N - 1; ++it) {
        // tree argmin over 8 local entries (tie->left == lowest index)
        unsigned bb[8];
#pragma unroll
        for (int k = 0; k < 8; k++) bb[k] = __float_as_uint(md[k]);
        unsigned l1b[4], l1i[4];
#pragma unroll
        for (int k = 0; k < 4; k++) {
            bool t = bb[2*k+1] < bb[2*k];
            l1b[k] = t ? bb[2*k+1] : bb[2*k];
            l1i[k] = t ? (unsigned)(2*k+1) : (unsigned)(2*k);
        }
        bool ta = l1b[1] < l1b[0];
        unsigned l2b0 = ta ? l1b[1] : l1b[0];
        unsigned l2i0 = ta ? l1i[1] : l1i[0];
        bool tb = l1b[3] < l1b[2];
        unsigned l2b1 = tb ? l1b[3] : l1b[2];
        unsigned l2i1 = tb ? l1i[3] : l1i[2];
        bool tc = l2b1 < l2b0;
        unsigned vb = tc ? l2b1 : l2b0;
        unsigned vi = (unsigned)(tid * 8) + (tc ? l2i1 : l2i0);

        unsigned m  = __reduce_min_sync(0xFFFFFFFFu, vb);
        unsigned c  = (vb == m) ? vi : 0xFFFFFFFFu;
        unsigned mi = __reduce_min_sync(0xFFFFFFFFu, c);
        if (lane == 0)
            wkey[it & 1][warp] = (((unsigned long long)m) << 32) | mi;
        __syncthreads();
        unsigned long long k2 = wkey[it & 1][lane & 15];
        unsigned b3 = (unsigned)(k2 >> 32);
        unsigned m2 = __reduce_min_sync(0xFFFFFFFFu, b3);
        unsigned c2 = (b3 == m2) ? (unsigned)k2 : 0xFFFFFFFFu;
        unsigned v  = __reduce_min_sync(0xFFFFFFFFu, c2);
        float d = __uint_as_float(m2);

        const float4* rowv = (const float4*)(g_D + (size_t)v * N);
        float4 ra = rowv[tid * 2];
        float4 rb = rowv[tid * 2 + 1];

        {
            bool iswin = (b3 == m2) && ((unsigned)k2 == v);
            unsigned b4 = iswin ? 0xFFFFFFFFu : b3;
            unsigned m3 = __reduce_min_sync(0xFFFFFFFFu, b4);
            unsigned c3 = (b4 == m3) ? (unsigned)k2 : 0xFFFFFFFFu;
            unsigned v2 = __reduce_min_sync(0xFFFFFFFFu, c3);
            v2 = (v2 > 4095u) ? 4095u : v2;
            const char* pf = (const char*)(g_D + (size_t)v2 * N) + tid * 32;
            asm volatile("prefetch.global.L1 [%0];" :: "l"(pf));
        }

        if ((v >> 3) == (unsigned)tid) {
            int k = (int)(v & 7u);
#pragma unroll
            for (int q = 0; q < 8; q++) if (q == k) {
                g_eu[it] = mf[q];
                md[q] = BIG;
            }
            g_ev[it] = (int)v;
            g_ed[it] = d;
            intree |= (1u << k);
        }
        float dr[8] = { ra.x, ra.y, ra.z, ra.w, rb.x, rb.y, rb.z, rb.w };
#pragma unroll
        for (int k = 0; k < 8; k++) {
            if (!((intree >> k) & 1) && dr[k] < md[k]) { md[k] = dr[k]; mf[k] = (int)v; }
        }
    }
}

// ---------------- kernel 4: STABLE bitonic sort of 4095 edges + outputs ----
__global__ void __launch_bounds__(1024) k_sort(float* __restrict__ out) {
    __shared__ unsigned long long key[N];
    int tid = threadIdx.x;
    for (int e = tid; e < N; e += 1024) {
        if (e < N - 1) {
            key[e] = (((unsigned long long)__float_as_uint(g_ed[e])) << 32)
                     | (unsigned)e;
        } else {
            key[e] = 0xFFFFFFFFFFFFFFFFull;
        }
    }
    __syncthreads();
    for (int sz = 2; sz <= N; sz <<= 1) {
        for (int j = sz >> 1; j > 0; j >>= 1) {
            for (int i = tid; i < N; i += 1024) {
                int l = i ^ j;
                if (l > i) {
                    bool asc = ((i & sz) == 0);
                    unsigned long long ki = key[i], kl = key[l];
                    if ((ki > kl) == asc) { key[i] = kl; key[l] = ki; }
                }
            }
            __syncthreads();
        }
    }
    for (int e = tid; e < N - 1; e += 1024) {
        unsigned long long k = key[e];
        int src = (int)(unsigned)(k & 0xFFFFFFFFu);
        float fd = __uint_as_float((unsigned)(k >> 32));
        int u = g_eu[src], v = g_ev[src];
        float fu = (float)u, fv = (float)v;
        out[OFF_EMST + 3 * e + 0] = fu;
        out[OFF_EMST + 3 * e + 1] = fv;
        out[OFF_EMST + 3 * e + 2] = fd;
        out[OFF_EU + e] = fu;
        out[OFF_EV + e] = fv;
        out[OFF_D + e] = fd;
        g_us[e] = u;
        g_vs[e] = v;
        g_ds[e] = fd;
    }
}

// ---------------- kernel 5: Kruskal, single thread, 4x unrolled ------------
__global__ void __launch_bounds__(1024) k_kruskal(const int* __restrict__ labels,
                                                  float* __restrict__ out) {
    extern __shared__ int sm[];
    int*   parent = sm;                       // N
    int*   counts = sm + N;                   // N*10
    int*   seu    = sm + N + N * NUM_LABELS;  // N
    int*   sev    = seu + N;                  // N
    float* sd     = (float*)(sev + N);        // N
    __shared__ int cbin[16];

    int tid = threadIdx.x;
    if (tid < 16) cbin[tid] = 0;
    for (int i = tid; i < N * NUM_LABELS; i += 1024) counts[i] = 0;
    __syncthreads();
    for (int n = tid; n < N; n += 1024) {
        parent[n] = n;
        int l = labels[n];
        counts[n * NUM_LABELS + l] = 1;
        atomicAdd(&cbin[l], 1);
    }
    for (int e = tid; e < N - 1; e += 1024) {
        seu[e] = g_us[e]; sev[e] = g_vs[e]; sd[e] = g_ds[e];
    }
    __syncthreads();
    if (tid != 0) return;

    float inv_tpf, inv_tnf;
    {
        long long tp = 0;
#pragma unroll
        for (int l = 0; l < NUM_LABELS; l++)
            tp += (long long)cbin[l] * (cbin[l] - 1) / 2;
        long long pairs = (long long)N * (N - 1) / 2;
        inv_tpf = 1.0f / (float)tp;
        inv_tnf = 1.0f / (float)(pairs - tp);
    }

#define KEDGE(E, ACC) do {                                                    \
        int x0 = seu[E];                                                      \
        int x1 = sev[E];                                                      \
        int p0 = parent[x0];                                                  \
        int p1 = parent[x1];                                                  \
        while (p0 != x0) { int g = parent[p0]; parent[x0] = g; x0 = p0; p0 = g; } \
        while (p1 != x1) { int g = parent[p1]; parent[x1] = g; x1 = p1; p1 = g; } \
        int a = x0, b = x1;                                                   \
        const int2* ra2 = (const int2*)(counts + a * NUM_LABELS);             \
        const int2* rb2 = (const int2*)(counts + b * NUM_LABELS);             \
        int2 av[5], bv[5], mg[5];                                             \
        int pos = 0, sa = 0, sb = 0;                                          \
        _Pragma("unroll")                                                     \
        for (int i = 0; i < 5; i++) { av[i] = ra2[i]; bv[i] = rb2[i]; }       \
        _Pragma("unroll")                                                     \
        for (int i = 0; i < 5; i++) {                                         \
            pos += av[i].x * bv[i].x + av[i].y * bv[i].y;                     \
            sa  += av[i].x + av[i].y;                                         \
            sb  += bv[i].x + bv[i].y;                                         \
            mg[i].x = av[i].x + bv[i].x;                                      \
            mg[i].y = av[i].y + bv[i].y;                                      \
        }                                                                     \
        int r  = (sa >= sb) ? a : b;                                          \
        int s2 = (sa >= sb) ? b : a;                                          \
        int2* rr2 = (int2*)(counts + r * NUM_LABELS);                         \
        int2* rs2 = (int2*)(counts + s2 * NUM_LABELS);                        \
        _Pragma("unroll")                                                     \
        for (int i = 0; i < 5; i++) { rr2[i] = mg[i]; rs2[i] = make_int2(0, 0); } \
        parent[s2] = r;                                                       \
        int neg = sa * sb - pos;                                              \
        float d = sd[E];                                                      \
        float rp = (float)pos * inv_tpf;                                      \
        float rn = (float)neg * inv_tnf;                                      \
        out[OFF_RP + (E)] = rp;                                               \
        out[OFF_RN + (E)] = rn;                                               \
        float mm = fmaxf(0.0f, 0.1f - d);                                     \
        ACC += (double)(rp * d * d + rn * mm * mm);                           \
    } while (0)

    double acc0 = 0.0, acc1 = 0.0, acc2 = 0.0, acc3 = 0.0;
    int e = 0;
    for (; e + 4 <= N - 1; e += 4) {
        KEDGE(e + 0, acc0);
        KEDGE(e + 1, acc1);
        KEDGE(e + 2, acc2);
        KEDGE(e + 3, acc3);
    }
    for (; e < N - 1; e++) KEDGE(e, acc0);
#undef KEDGE
    out[0] = (float)((acc0 + acc1) + (acc2 + acc3));
}

// ---------------- launch ----------------
extern "C" void kernel_launch(void* const* d_in, const int* in_sizes, int n_in,
                              void* d_out, int out_size) {
    const float* input  = (const float*)d_in[0];
    const int*   target = (const int*)d_in[1];
    float* out = (float*)d_out;

    static const size_t KSMEM = (size_t)(N + N * NUM_LABELS + 3 * N) * 4;
    cudaFuncSetAttribute(k_kruskal, cudaFuncAttributeMaxDynamicSharedMemorySize,
                         (int)KSMEM);

    k_pts<<<4, 1024>>>(input);
    k_dist<<<dim3(128, 128), dim3(32, 8)>>>();
    k_prim<<<1, 512>>>();
    k_sort<<<1, 1024>>>(out);
    k_kruskal<<<1, 1024, KSMEM>>>(target, out);
}